// round 13
// baseline (speedup 1.0000x reference)
#include <cuda_runtime.h>
#include <math.h>

// Problem shape (fixed by setup_inputs)
#define Bb   32
#define Hh   64
#define Ww   48
#define Cc   256
#define Dd   32
#define BG   256            // Bb * groups(8)
#define NPIX (Hh*Ww)        // 3072
#define LN_EPS 1e-3f

// Scratch (device globals — no allocation allowed)
__device__ float g_w2[BG*NPIX];    // per-pixel w2 = rs*(c·y - mu*csum) + cb
__device__ float g_weff[BG*9*Dd];  // x11-projected conv3x3 kernel
__device__ float g_beff[BG];       // dot(x11, conv3x3_b)

__device__ __forceinline__ float wsum(float v){
#pragma unroll
    for (int o = 16; o; o >>= 1) v += __shfl_xor_sync(0xffffffffu, v, o);
    return v;
}
__device__ __forceinline__ float wmax(float v){
#pragma unroll
    for (int o = 16; o; o >>= 1) v = fmaxf(v, __shfl_xor_sync(0xffffffffu, v, o));
    return v;
}

// Dynamic smem layout for fused kernel (floats):
#define F_ROW   0                  // s_row[64][32]
#define F_COLP  2048               // s_colp[4][48][32]
#define F_XH    8192               // s_xh[64][32]
#define F_XW    10240              // s_xw[48][32]
#define F_W1    11776              // smW[1024]
#define F_S9    12800              // smS[288]
#define F_SA    13088              // sA[16][32]
#define F_SB    13600              // sB[16]
#define F_X11   13616              // x11[32]
#define F_C     13648              // s_c[32]  (x21*gamma)
#define F_SC    13680              // s_scal[2] (csum, cb)
#define F_TOTAL 13684              // floats -> 54736 bytes

// ---------------------------------------------------------------------------
// Fused pass 1+2+3+4 (+ w2 field): one block (512 thr, 16 warps) per bg.
// ---------------------------------------------------------------------------
__global__ void __launch_bounds__(512, 1)
fused1234(const float* __restrict__ x,
          const float* __restrict__ w1x1,
          const float* __restrict__ b1,
          const float* __restrict__ w3,
          const float* __restrict__ b3,
          const float* __restrict__ gamma,
          const float* __restrict__ beta)
{
    extern __shared__ float sm[];
    float (*s_row)[Dd]       = (float(*)[Dd])(sm + F_ROW);
    float (*s_colp)[Ww][Dd]  = (float(*)[Ww][Dd])(sm + F_COLP);
    float (*s_xh)[Dd]        = (float(*)[Dd])(sm + F_XH);
    float (*s_xw)[Dd]        = (float(*)[Dd])(sm + F_XW);
    float *smW = sm + F_W1;
    float *smS = sm + F_S9;
    float (*sA)[Dd]          = (float(*)[Dd])(sm + F_SA);
    float *sB  = sm + F_SB;
    float *x11 = sm + F_X11;
    float *s_c = sm + F_C;
    float *s_scal = sm + F_SC;

    int bg = blockIdx.x;
    int b = bg >> 3, gi = bg & 7;
    int tid = threadIdx.x, lane = tid & 31, warp = tid >> 5;   // 16 warps
    int sg = lane >> 3, ch0 = (lane & 7) * 4;
    const float* xg = x + ((size_t)b*Hh)*Ww*Cc + gi*Dd + ch0;  // float4 base
    const float* xb = x + ((size_t)b*Hh)*Ww*Cc + gi*Dd + lane; // scalar base

    // stage conv1x1 weights (sync provided by the col-reduce rounds below)
    for (int i = tid; i < Dd*Dd; i += 512) smW[i] = w1x1[i];

    // ---- Phase A: warp owns rows warp*4..+3; register col partials ----
    float4 cacc[12];
#pragma unroll
    for (int s = 0; s < 12; ++s) cacc[s] = make_float4(0.f,0.f,0.f,0.f);
    {
        int r0 = warp * 4;
#pragma unroll
        for (int r = 0; r < 4; ++r) {
            int row = r0 + r;
            const float* rp = xg + (size_t)row*Ww*Cc;
            float4 racc = make_float4(0.f,0.f,0.f,0.f);
#pragma unroll
            for (int s = 0; s < 12; ++s) {
                float4 v = *(const float4*)(rp + (size_t)(s*4 + sg)*Cc);
                cacc[s].x += v.x; cacc[s].y += v.y; cacc[s].z += v.z; cacc[s].w += v.w;
                racc.x += v.x; racc.y += v.y; racc.z += v.z; racc.w += v.w;
            }
#pragma unroll
            for (int o = 8; o <= 16; o <<= 1) {
                racc.x += __shfl_xor_sync(0xffffffffu, racc.x, o);
                racc.y += __shfl_xor_sync(0xffffffffu, racc.y, o);
                racc.z += __shfl_xor_sync(0xffffffffu, racc.z, o);
                racc.w += __shfl_xor_sync(0xffffffffu, racc.w, o);
            }
            if (sg == 0) {
                racc.x *= (1.f/Ww); racc.y *= (1.f/Ww); racc.z *= (1.f/Ww); racc.w *= (1.f/Ww);
                *(float4*)&s_row[row][ch0] = racc;
            }
        }
    }
    // staged (atomic-free) cross-warp col reduction into 4 slots
    {
        int slot = warp & 3, grp = warp >> 2;
        if (grp == 0) {
#pragma unroll
            for (int s = 0; s < 12; ++s)
                *(float4*)&s_colp[slot][s*4 + sg][ch0] = cacc[s];
        }
        __syncthreads();
#pragma unroll
        for (int rd = 1; rd < 4; ++rd) {
            if (grp == rd) {
#pragma unroll
                for (int s = 0; s < 12; ++s) {
                    float4 t = *(float4*)&s_colp[slot][s*4 + sg][ch0];
                    t.x += cacc[s].x; t.y += cacc[s].y; t.z += cacc[s].z; t.w += cacc[s].w;
                    *(float4*)&s_colp[slot][s*4 + sg][ch0] = t;
                }
            }
            __syncthreads();
        }
    }
    // now col SUM (over 64 rows) of [w][ch] = sum over 4 slots

    // ---- Phase B (warps 1..15) / Phase C (warp 0), concurrent ----
    if (warp > 0) {
        float bias = b1[lane];
        for (int p = warp - 1; p < Hh + Ww; p += 15) {
            float v;
            if (p < Hh) v = s_row[p][lane];
            else {
                int w = p - Hh;
                v = (s_colp[0][w][lane] + s_colp[1][w][lane]
                   + s_colp[2][w][lane] + s_colp[3][w][lane]) * (1.0f/Hh);
            }
            float acc = bias;
#pragma unroll
            for (int i = 0; i < Dd; ++i) {
                float vi = __shfl_sync(0xffffffffu, v, i);
                acc += vi * smW[i*Dd + lane];
            }
            float s = 1.f/(1.f + expf(-acc));
            if (p < Hh) s_xh[p][lane] = s;
            else        s_xw[p-Hh][lane] = s;
        }
    } else {
        int i = lane;
        float T = 0.f;
#pragma unroll 8
        for (int h = 0; h < Hh; ++h) T += s_row[h][i];
        T *= (float)Ww;
        float R0 = s_row[0     ][i] * (float)Ww;
        float RL = s_row[Hh - 1][i] * (float)Ww;
        float C0 = s_colp[0][0][i] + s_colp[1][0][i] + s_colp[2][0][i] + s_colp[3][0][i];
        float CL = s_colp[0][Ww-1][i] + s_colp[1][Ww-1][i] + s_colp[2][Ww-1][i] + s_colp[3][Ww-1][i];
        float ctl = xb[0];
        float ctr = xb[(size_t)(Ww-1)*Cc];
        float cbl = xb[((size_t)(Hh-1)*Ww)*Cc];
        float cbr = xb[((size_t)(Hh-1)*Ww + (Ww-1))*Cc];
#pragma unroll
        for (int dy = -1; dy <= 1; ++dy) {
#pragma unroll
            for (int dx = -1; dx <= 1; ++dx) {
                float eR = (dy == -1) ? RL : (dy == 1) ? R0 : 0.f;
                float eC = (dx == -1) ? CL : (dx == 1) ? C0 : 0.f;
                float corner = 0.f;
                if (dy == -1 && dx == -1) corner = cbr;
                if (dy == -1 && dx ==  1) corner = cbl;
                if (dy ==  1 && dx == -1) corner = ctr;
                if (dy ==  1 && dx ==  1) corner = ctl;
                smS[((dy+1)*3 + (dx+1))*Dd + i] = T - eR - eC + corner;
            }
        }
        __syncwarp();
        int e = lane;
        float acc = 0.f;
        for (int k = 0; k < 9; ++k) {
#pragma unroll
            for (int ii = 0; ii < Dd; ++ii)
                acc += w3[(k*Dd + ii)*Dd + e] * smS[k*Dd + ii];
        }
        float m2 = acc * (1.f/NPIX) + b3[e];
        float mx = wmax(m2);
        float pz = expf(m2 - mx);
        float ps = wsum(pz);
        float x21 = pz/ps;
        float cv = x21 * gamma[e];
        s_c[e] = cv;
        float cs  = wsum(cv);
        float cbv = wsum(x21 * beta[e]);
        if (e == 0) { s_scal[0] = cs; s_scal[1] = cbv; }
    }
    __syncthreads();

    // ---- Phase D: LN-stat sweep + per-pixel w2 field ----
    {
        float4 cvq = *(const float4*)&s_c[ch0];
        float csum = s_scal[0], cb = s_scal[1];
        float4 accA = make_float4(0.f,0.f,0.f,0.f);
        float accB = 0.f;
        int p0 = warp * 192;
        float* w2out = g_w2 + bg*NPIX;
#pragma unroll 2
        for (int j = 0; j < 192; j += 4) {
            int p = p0 + j + sg;
            int h = p / Ww, w = p - h*Ww;
            float4 gx = *(const float4*)(xg + (size_t)p*Cc);
            float4 xh = *(const float4*)&s_xh[h][ch0];
            float4 xw = *(const float4*)&s_xw[w][ch0];
            float4 y;
            y.x = gx.x*xh.x*xw.x; y.y = gx.y*xh.y*xw.y;
            y.z = gx.z*xh.z*xw.z; y.w = gx.w*xh.w*xw.w;
            float a  = (y.x + y.y) + (y.z + y.w);
            float bq = (y.x*y.x + y.y*y.y) + (y.z*y.z + y.w*y.w);
            float cy = (cvq.x*y.x + cvq.y*y.y) + (cvq.z*y.z + cvq.w*y.w);
#pragma unroll
            for (int o = 4; o; o >>= 1) {
                a  += __shfl_xor_sync(0xffffffffu, a,  o);
                bq += __shfl_xor_sync(0xffffffffu, bq, o);
                cy += __shfl_xor_sync(0xffffffffu, cy, o);
            }
            float mu = a * (1.f/Dd);
            float var = bq * (1.f/Dd) - mu*mu;
            float rs = rsqrtf(var + LN_EPS);
            accA.x += rs*y.x; accA.y += rs*y.y; accA.z += rs*y.z; accA.w += rs*y.w;
            accB += rs*mu;
            float w2v = rs * (cy - mu*csum) + cb;
            if ((lane & 7) == 0) w2out[p] = w2v;
        }
#pragma unroll
        for (int o = 8; o <= 16; o <<= 1) {
            accA.x += __shfl_xor_sync(0xffffffffu, accA.x, o);
            accA.y += __shfl_xor_sync(0xffffffffu, accA.y, o);
            accA.z += __shfl_xor_sync(0xffffffffu, accA.z, o);
            accA.w += __shfl_xor_sync(0xffffffffu, accA.w, o);
        }
        if (sg == 0) *(float4*)&sA[warp][ch0] = accA;
        float bt = wsum(accB) * 0.125f;   // each pixel counted by 8 lanes
        if (lane == 0) sB[warp] = bt;
    }
    __syncthreads();

    // ---- Phase E: x11 softmax + beff (warp 0), then weff (288 threads) ----
    if (warp == 0) {
        int e = lane;
        float A = 0.f, Bs = 0.f;
#pragma unroll
        for (int k = 0; k < 16; ++k) { A += sA[k][e]; Bs += sB[k]; }
        float v = gamma[e] * (A - Bs) * (1.f/NPIX) + beta[e];
        float mx = wmax(v);
        float p = expf(v - mx);
        float ps = wsum(p);
        float xv = p/ps;
        x11[e] = xv;
        float be = wsum(xv * b3[e]);
        if (e == 0) g_beff[bg] = be;
    }
    __syncthreads();
    if (tid < 288) {
        int k = tid >> 5, i = tid & 31;
        const float4* wrow = (const float4*)(w3 + (size_t)(k*Dd + i)*Dd);
        float acc = 0.f;
#pragma unroll
        for (int e4 = 0; e4 < 8; ++e4) {
            float4 wv = __ldg(&wrow[e4]);
            acc += wv.x*x11[e4*4+0] + wv.y*x11[e4*4+1]
                 + wv.z*x11[e4*4+2] + wv.w*x11[e4*4+3];
        }
        g_weff[(bg*9 + k)*Dd + i] = acc;
    }
}

// ---------------------------------------------------------------------------
// Pass 5: register column march, weff in smem, SHUFFLE neighbor sharing.
// Block = 384 thr (12 warps) = full 48-column row; marches a 32-row band.
// blockIdx: [bg (8b)] [band (1b)]  -> grid = BG*2
// vm/vp come from the adjacent subgroup's v0 via __shfl (edges: 128B loads).
// ---------------------------------------------------------------------------
__global__ void __launch_bounds__(384, 2)
pass5(const float* __restrict__ x, float* __restrict__ out)
{
    __shared__ __align__(16) float s_wk[9][Dd];   // 1152 B

    int bg = blockIdx.x >> 1;
    int r0 = (blockIdx.x & 1) * 32;
    int b = bg >> 3, gi = bg & 7;
    int tid = threadIdx.x;
    int lane = tid & 31, warp = tid >> 5;   // 12 warps
    int sg = lane >> 3, ch0 = (lane & 7) * 4;
    int w = warp*4 + sg;                    // output column 0..47
    const int WC4 = Ww*Cc/4;                // float4 row stride

    if (tid < 288) s_wk[tid >> 5][tid & 31] = g_weff[bg*9*Dd + tid];
    __syncthreads();

    float beff = g_beff[bg];
    bool edge_m = (sg == 0) && (warp > 0);        // load w-1 (column warp*4-1)
    bool edge_p = (sg == 3) && (warp < 11);       // load w+1 (column warp*4+4)

    // running pointers
    const float4* rq = (const float4*)(x + ((size_t)b*Hh)*Ww*Cc + gi*Dd + ch0)
                       + (ptrdiff_t)(r0-1)*WC4 + w*(Cc/4);   // source row r0-1
    float4* oq = (float4*)(out + ((size_t)b*Hh)*Ww*Cc + gi*Dd + ch0)
                 + (ptrdiff_t)r0*WC4 + w*(Cc/4);             // output row r0
    const float* w2p_ptr = g_w2 + bg*NPIX + r0*Ww + w;       // w2 prefetch row r0

    const float4 z = make_float4(0.f,0.f,0.f,0.f);
    float4 a0 = z, a1 = z, pend = z;
    float4 gx_d1 = z, gx_d2 = z;
    float w2p = 0.f;

    for (int R = r0-1; R <= r0+33; ++R) {
        // 1) loads for source row R: center column + warp-edge columns only
        float4 vm = z, v0 = z, vp = z;
        if ((unsigned)R < (unsigned)Hh && R <= r0+32) {
            v0 = rq[0];
            if (edge_m) vm = rq[-(Cc/4)];
            if (edge_p) vp = rq[ (Cc/4)];
        }
        rq += WC4;
        // 2) prefetch w2 for row R-1 (used at next iteration's emission)
        float w2_pf = 0.f;
        if ((unsigned)(R-1-r0) < 32u) { w2_pf = *w2p_ptr; w2p_ptr += Ww; }

        // 3) emission for output row R-2 (depends on previous iterations only)
        if (R >= r0+2) {
            float conv = (pend.x + pend.y) + (pend.z + pend.w);
#pragma unroll
            for (int o2 = 4; o2; o2 >>= 1)
                conv += __shfl_xor_sync(0xffffffffu, conv, o2);
            float t = conv + beff + w2p;
            float gate = __fdividef(1.f, 1.f + __expf(-t));
            float4 o4;
            o4.x = gx_d2.x*gate; o4.y = gx_d2.y*gate;
            o4.z = gx_d2.z*gate; o4.w = gx_d2.w*gate;
            __stcs(oq, o4);
            oq += WC4;
        }

        // 3b) neighbor sharing: vm/vp from adjacent subgroup's v0
        {
            float tx = __shfl_up_sync(0xffffffffu, v0.x, 8);
            float ty = __shfl_up_sync(0xffffffffu, v0.y, 8);
            float tz = __shfl_up_sync(0xffffffffu, v0.z, 8);
            float tw = __shfl_up_sync(0xffffffffu, v0.w, 8);
            if (sg != 0) { vm.x = tx; vm.y = ty; vm.z = tz; vm.w = tw; }
            tx = __shfl_down_sync(0xffffffffu, v0.x, 8);
            ty = __shfl_down_sync(0xffffffffu, v0.y, 8);
            tz = __shfl_down_sync(0xffffffffu, v0.z, 8);
            tw = __shfl_down_sync(0xffffffffu, v0.w, 8);
            if (sg != 3) { vp.x = tx; vp.y = ty; vp.z = tz; vp.w = tw; }
        }

        // 4) row-dots for source row R; weights streamed from smem
        float4 k0 = *(const float4*)&s_wk[0][ch0];
        float4 k1 = *(const float4*)&s_wk[1][ch0];
        float4 k2 = *(const float4*)&s_wk[2][ch0];
        float4 rd0;
        rd0.x = k0.x*vm.x + k1.x*v0.x + k2.x*vp.x;
        rd0.y = k0.y*vm.y + k1.y*v0.y + k2.y*vp.y;
        rd0.z = k0.z*vm.z + k1.z*v0.z + k2.z*vp.z;
        rd0.w = k0.w*vm.w + k1.w*v0.w + k2.w*vp.w;
        k0 = *(const float4*)&s_wk[3][ch0];
        k1 = *(const float4*)&s_wk[4][ch0];
        k2 = *(const float4*)&s_wk[5][ch0];
        float4 rd1;
        rd1.x = k0.x*vm.x + k1.x*v0.x + k2.x*vp.x;
        rd1.y = k0.y*vm.y + k1.y*v0.y + k2.y*vp.y;
        rd1.z = k0.z*vm.z + k1.z*v0.z + k2.z*vp.z;
        rd1.w = k0.w*vm.w + k1.w*v0.w + k2.w*vp.w;
        k0 = *(const float4*)&s_wk[6][ch0];
        k1 = *(const float4*)&s_wk[7][ch0];
        k2 = *(const float4*)&s_wk[8][ch0];
        float4 rd2;
        rd2.x = k0.x*vm.x + k1.x*v0.x + k2.x*vp.x;
        rd2.y = k0.y*vm.y + k1.y*v0.y + k2.y*vp.y;
        rd2.z = k0.z*vm.z + k1.z*v0.z + k2.z*vp.z;
        rd2.w = k0.w*vm.w + k1.w*v0.w + k2.w*vp.w;

        // 5) rotate pipeline state
        pend.x = a0.x + rd2.x; pend.y = a0.y + rd2.y;
        pend.z = a0.z + rd2.z; pend.w = a0.w + rd2.w;
        a0.x = a1.x + rd1.x; a0.y = a1.y + rd1.y;
        a0.z = a1.z + rd1.z; a0.w = a1.w + rd1.w;
        a1 = rd0;
        gx_d2 = gx_d1;
        gx_d1 = v0;
        w2p = w2_pf;
    }
}

// ---------------------------------------------------------------------------
extern "C" void kernel_launch(void* const* d_in, const int* in_sizes, int n_in,
                              void* d_out, int out_size)
{
    const float* x   = (const float*)d_in[0];
    const float* w1  = (const float*)d_in[1];
    const float* b1  = (const float*)d_in[2];
    const float* w3  = (const float*)d_in[3];
    const float* b3  = (const float*)d_in[4];
    const float* gm  = (const float*)d_in[5];
    const float* bt  = (const float*)d_in[6];
    float* out = (float*)d_out;

    static int configured = 0;
    if (!configured) {
        cudaFuncSetAttribute(fused1234, cudaFuncAttributeMaxDynamicSharedMemorySize,
                             F_TOTAL * 4);
        configured = 1;
    }

    fused1234<<<BG, 512, F_TOTAL*4>>>(x, w1, b1, w3, b3, gm, bt);
    pass5<<<BG*2, 384>>>(x, out);
}

// round 14
// speedup vs baseline: 1.0495x; 1.0495x over previous
#include <cuda_runtime.h>
#include <math.h>

// Problem shape (fixed by setup_inputs)
#define Bb   32
#define Hh   64
#define Ww   48
#define Cc   256
#define Dd   32
#define BG   256            // Bb * groups(8)
#define NPIX (Hh*Ww)        // 3072
#define LN_EPS 1e-3f

__device__ __forceinline__ float wsum(float v){
#pragma unroll
    for (int o = 16; o; o >>= 1) v += __shfl_xor_sync(0xffffffffu, v, o);
    return v;
}
__device__ __forceinline__ float wmax(float v){
#pragma unroll
    for (int o = 16; o; o >>= 1) v = fmaxf(v, __shfl_xor_sync(0xffffffffu, v, o));
    return v;
}

// Dynamic smem layout (floats):
#define F_ROW   0                  // s_row[64][32]
#define F_COLP  2048               // s_colp[4][48][32]; AFTER Phase C reused as s_w2[3072]
#define F_XH    8192               // s_xh[64][32]
#define F_XW    10240              // s_xw[48][32]
#define F_W1    11776              // smW[1024]; AFTER Phase B reused as s_weff[288]
#define F_S9    12800              // smS[288]
#define F_SA    13088              // sA[16][32]
#define F_SB    13600              // sB[16]
#define F_X11   13616              // x11[32]
#define F_C     13648              // s_c[32]  (x21*gamma)
#define F_SC    13680              // s_scal[4] (csum, cb, beff)
#define F_TOTAL 13684              // floats -> 54736 bytes

// ---------------------------------------------------------------------------
// GRAND FUSED kernel: pools, gates, x21/x11 softmaxes, LN stats, w2 field,
// projected conv + gate + output — one block (512 thr, 16 warps) per bg.
// launch_bounds(512,2): 2 blocks/SM -> all 256 blocks in ONE wave.
// ---------------------------------------------------------------------------
__global__ void __launch_bounds__(512, 2)
fused_all(const float* __restrict__ x,
          const float* __restrict__ w1x1,
          const float* __restrict__ b1,
          const float* __restrict__ w3,
          const float* __restrict__ b3,
          const float* __restrict__ gamma,
          const float* __restrict__ beta,
          float* __restrict__ out)
{
    extern __shared__ float sm[];
    float (*s_row)[Dd]       = (float(*)[Dd])(sm + F_ROW);
    float (*s_colp)[Ww][Dd]  = (float(*)[Ww][Dd])(sm + F_COLP);
    float (*s_xh)[Dd]        = (float(*)[Dd])(sm + F_XH);
    float (*s_xw)[Dd]        = (float(*)[Dd])(sm + F_XW);
    float *smW = sm + F_W1;
    float *smS = sm + F_S9;
    float (*sA)[Dd]          = (float(*)[Dd])(sm + F_SA);
    float *sB  = sm + F_SB;
    float *x11 = sm + F_X11;
    float *s_c = sm + F_C;
    float *s_scal = sm + F_SC;
    float *s_w2   = sm + F_COLP;   // overlay (valid after Phase C)
    float *s_weff = sm + F_W1;     // overlay (valid after Phase B)

    int bg = blockIdx.x;
    int b = bg >> 3, gi = bg & 7;
    int tid = threadIdx.x, lane = tid & 31, warp = tid >> 5;   // 16 warps
    int sg = lane >> 3, ch0 = (lane & 7) * 4;
    const float* xg = x + ((size_t)b*Hh)*Ww*Cc + gi*Dd + ch0;  // float4 base
    const float* xb = x + ((size_t)b*Hh)*Ww*Cc + gi*Dd + lane; // scalar base

    // stage conv1x1 weights (sync provided by the staged col-reduce below)
    for (int i = tid; i < Dd*Dd; i += 512) smW[i] = w1x1[i];

    // ---- Phase A: row means + col sums. Superslab structure (low regs). ----
    {
        float4 racc[4];
#pragma unroll
        for (int rr = 0; rr < 4; ++rr) racc[rr] = make_float4(0.f,0.f,0.f,0.f);
        int r0w = warp * 4;
        int slot = warp & 3, grp = warp >> 2;
#pragma unroll
        for (int ss = 0; ss < 3; ++ss) {
            float4 cacc[4];
#pragma unroll
            for (int s = 0; s < 4; ++s) cacc[s] = make_float4(0.f,0.f,0.f,0.f);
#pragma unroll
            for (int rr = 0; rr < 4; ++rr) {
                const float* rp = xg + (size_t)(r0w + rr)*Ww*Cc;
#pragma unroll
                for (int s = 0; s < 4; ++s) {
                    float4 v = *(const float4*)(rp + (size_t)(ss*16 + s*4 + sg)*Cc);
                    cacc[s].x += v.x; cacc[s].y += v.y; cacc[s].z += v.z; cacc[s].w += v.w;
                    racc[rr].x += v.x; racc[rr].y += v.y; racc[rr].z += v.z; racc[rr].w += v.w;
                }
            }
            // staged atomic-free cross-warp accumulation into s_colp[slot]
#pragma unroll
            for (int rd = 0; rd < 4; ++rd) {
                if (grp == rd) {
#pragma unroll
                    for (int s = 0; s < 4; ++s) {
                        float4* dst = (float4*)&s_colp[slot][ss*16 + s*4 + sg][ch0];
                        if (rd == 0) *dst = cacc[s];
                        else {
                            float4 t = *dst;
                            t.x += cacc[s].x; t.y += cacc[s].y;
                            t.z += cacc[s].z; t.w += cacc[s].w;
                            *dst = t;
                        }
                    }
                }
                __syncthreads();
            }
        }
        // row means
#pragma unroll
        for (int rr = 0; rr < 4; ++rr) {
            float4 rv = racc[rr];
#pragma unroll
            for (int o = 8; o <= 16; o <<= 1) {
                rv.x += __shfl_xor_sync(0xffffffffu, rv.x, o);
                rv.y += __shfl_xor_sync(0xffffffffu, rv.y, o);
                rv.z += __shfl_xor_sync(0xffffffffu, rv.z, o);
                rv.w += __shfl_xor_sync(0xffffffffu, rv.w, o);
            }
            if (sg == 0) {
                rv.x *= (1.f/Ww); rv.y *= (1.f/Ww); rv.z *= (1.f/Ww); rv.w *= (1.f/Ww);
                *(float4*)&s_row[r0w + rr][ch0] = rv;
            }
        }
    }
    __syncthreads();

    // ---- Phase B (warps 1..15) / Phase C (warp 0), concurrent ----
    if (warp > 0) {
        float bias = b1[lane];
        for (int p = warp - 1; p < Hh + Ww; p += 15) {
            float v;
            if (p < Hh) v = s_row[p][lane];
            else {
                int w = p - Hh;
                v = (s_colp[0][w][lane] + s_colp[1][w][lane]
                   + s_colp[2][w][lane] + s_colp[3][w][lane]) * (1.0f/Hh);
            }
            float acc = bias;
#pragma unroll
            for (int i = 0; i < Dd; ++i) {
                float vi = __shfl_sync(0xffffffffu, v, i);
                acc += vi * smW[i*Dd + lane];
            }
            float s = 1.f/(1.f + expf(-acc));
            if (p < Hh) s_xh[p][lane] = s;
            else        s_xw[p-Hh][lane] = s;
        }
    } else {
        int i = lane;
        float T = 0.f;
#pragma unroll 8
        for (int h = 0; h < Hh; ++h) T += s_row[h][i];
        T *= (float)Ww;
        float R0 = s_row[0     ][i] * (float)Ww;
        float RL = s_row[Hh - 1][i] * (float)Ww;
        float C0 = s_colp[0][0][i] + s_colp[1][0][i] + s_colp[2][0][i] + s_colp[3][0][i];
        float CL = s_colp[0][Ww-1][i] + s_colp[1][Ww-1][i] + s_colp[2][Ww-1][i] + s_colp[3][Ww-1][i];
        float ctl = xb[0];
        float ctr = xb[(size_t)(Ww-1)*Cc];
        float cbl = xb[((size_t)(Hh-1)*Ww)*Cc];
        float cbr = xb[((size_t)(Hh-1)*Ww + (Ww-1))*Cc];
#pragma unroll
        for (int dy = -1; dy <= 1; ++dy) {
#pragma unroll
            for (int dx = -1; dx <= 1; ++dx) {
                float eR = (dy == -1) ? RL : (dy == 1) ? R0 : 0.f;
                float eC = (dx == -1) ? CL : (dx == 1) ? C0 : 0.f;
                float corner = 0.f;
                if (dy == -1 && dx == -1) corner = cbr;
                if (dy == -1 && dx ==  1) corner = cbl;
                if (dy ==  1 && dx == -1) corner = ctr;
                if (dy ==  1 && dx ==  1) corner = ctl;
                smS[((dy+1)*3 + (dx+1))*Dd + i] = T - eR - eC + corner;
            }
        }
        __syncwarp();
        int e = lane;
        float acc = 0.f;
        for (int k = 0; k < 9; ++k) {
#pragma unroll
            for (int ii = 0; ii < Dd; ++ii)
                acc += w3[(k*Dd + ii)*Dd + e] * smS[k*Dd + ii];
        }
        float m2 = acc * (1.f/NPIX) + b3[e];
        float mx = wmax(m2);
        float pz = expf(m2 - mx);
        float ps = wsum(pz);
        float x21 = pz/ps;
        float cv = x21 * gamma[e];
        s_c[e] = cv;
        float cs  = wsum(cv);
        float cbv = wsum(x21 * beta[e]);
        if (e == 0) { s_scal[0] = cs; s_scal[1] = cbv; }
    }
    __syncthreads();
    // s_colp is dead from here on: its space becomes s_w2

    // ---- Phase D: LN-stat sweep + per-pixel w2 field (into smem) ----
    {
        float4 cvq = *(const float4*)&s_c[ch0];
        float csum = s_scal[0], cb = s_scal[1];
        float4 accA = make_float4(0.f,0.f,0.f,0.f);
        float accB = 0.f;
        int p0 = warp * 192;
#pragma unroll 2
        for (int j = 0; j < 192; j += 4) {
            int p = p0 + j + sg;
            int h = p / Ww, w = p - h*Ww;
            float4 gx = *(const float4*)(xg + (size_t)p*Cc);
            float4 xh = *(const float4*)&s_xh[h][ch0];
            float4 xw = *(const float4*)&s_xw[w][ch0];
            float4 y;
            y.x = gx.x*xh.x*xw.x; y.y = gx.y*xh.y*xw.y;
            y.z = gx.z*xh.z*xw.z; y.w = gx.w*xh.w*xw.w;
            float a  = (y.x + y.y) + (y.z + y.w);
            float bq = (y.x*y.x + y.y*y.y) + (y.z*y.z + y.w*y.w);
            float cy = (cvq.x*y.x + cvq.y*y.y) + (cvq.z*y.z + cvq.w*y.w);
#pragma unroll
            for (int o = 4; o; o >>= 1) {
                a  += __shfl_xor_sync(0xffffffffu, a,  o);
                bq += __shfl_xor_sync(0xffffffffu, bq, o);
                cy += __shfl_xor_sync(0xffffffffu, cy, o);
            }
            float mu = a * (1.f/Dd);
            float var = bq * (1.f/Dd) - mu*mu;
            float rs = rsqrtf(var + LN_EPS);
            accA.x += rs*y.x; accA.y += rs*y.y; accA.z += rs*y.z; accA.w += rs*y.w;
            accB += rs*mu;
            float w2v = rs * (cy - mu*csum) + cb;
            if ((lane & 7) == 0) s_w2[p] = w2v;
        }
#pragma unroll
        for (int o = 8; o <= 16; o <<= 1) {
            accA.x += __shfl_xor_sync(0xffffffffu, accA.x, o);
            accA.y += __shfl_xor_sync(0xffffffffu, accA.y, o);
            accA.z += __shfl_xor_sync(0xffffffffu, accA.z, o);
            accA.w += __shfl_xor_sync(0xffffffffu, accA.w, o);
        }
        if (sg == 0) *(float4*)&sA[warp][ch0] = accA;
        float bt = wsum(accB) * 0.125f;   // each pixel counted by 8 lanes
        if (lane == 0) sB[warp] = bt;
    }
    __syncthreads();

    // ---- Phase E: x11 softmax + beff (warp 0), then weff into smem ----
    if (warp == 0) {
        int e = lane;
        float A = 0.f, Bs = 0.f;
#pragma unroll
        for (int k = 0; k < 16; ++k) { A += sA[k][e]; Bs += sB[k]; }
        float v = gamma[e] * (A - Bs) * (1.f/NPIX) + beta[e];
        float mx = wmax(v);
        float p = expf(v - mx);
        float ps = wsum(p);
        float xv = p/ps;
        x11[e] = xv;
        float be = wsum(xv * b3[e]);
        if (e == 0) s_scal[2] = be;
    }
    __syncthreads();
    if (tid < 288) {
        const float4* wrow = (const float4*)(w3 + (size_t)tid*Dd);
        float acc = 0.f;
#pragma unroll
        for (int e4 = 0; e4 < 8; ++e4) {
            float4 wv = __ldg(&wrow[e4]);
            acc += wv.x*x11[e4*4+0] + wv.y*x11[e4*4+1]
                 + wv.z*x11[e4*4+2] + wv.w*x11[e4*4+3];
        }
        s_weff[tid] = acc;   // overlays smW (dead after Phase B)
    }
    __syncthreads();

    // ---- Phase F: conv march along w + gate + output.
    // 16 warps x 4 rows = 64 rows; rotating accumulators over columns. ----
    {
        int r = warp*4 + sg;                       // 0..63
        const int C4 = Cc/4, RS = Ww*(Cc/4);
        const float4* rq = (const float4*)(x + ((size_t)b*Hh + r)*Ww*Cc + gi*Dd + ch0);
        float4* oq = (float4*)(out + ((size_t)b*Hh + r)*Ww*Cc + gi*Dd + ch0);
        const float* w2row = s_w2 + r*Ww;
        const float4* wf = (const float4*)s_weff;
        int wki = ch0 >> 2;                        // float4 index within 32-ch row
        float beff = s_scal[2];
        bool up = (r > 0), dn = (r < Hh-1);

        const float4 z = make_float4(0.f,0.f,0.f,0.f);
        float4 a0 = z, a1 = z, pend = z, g1 = z, g2 = z;
        float w2p = 0.f;

        for (int W = 0; W < 50; ++W) {
            // loads for source column W (rows r-1, r, r+1)
            float4 v0 = z, vm = z, vp = z;
            if (W < Ww) {
                v0 = rq[0];
                if (up) vm = rq[-RS];
                if (dn) vp = rq[ RS];
            }
            rq += C4;
            // prefetch w2 for output column W-1 (consumed next iteration)
            float w2pf = 0.f;
            if ((unsigned)(W-1) < (unsigned)Ww) w2pf = w2row[W-1];

            // emission for output column W-2
            if (W >= 2) {
                float conv = (pend.x + pend.y) + (pend.z + pend.w);
                conv += __shfl_xor_sync(0xffffffffu, conv, 4);
                conv += __shfl_xor_sync(0xffffffffu, conv, 2);
                conv += __shfl_xor_sync(0xffffffffu, conv, 1);
                float gate = __fdividef(1.f, 1.f + __expf(-(conv + beff + w2p)));
                float4 o4;
                o4.x = g2.x*gate; o4.y = g2.y*gate; o4.z = g2.z*gate; o4.w = g2.w*gate;
                __stcs(oq, o4);
                oq += C4;
            }

            // column-dots: taps k=(dy+1)*3+j ; vm:dy=-1, v0:dy=0, vp:dy=+1
            float4 km, k0, kp, rA, rB, rC;
            km = wf[2*8+wki]; k0 = wf[5*8+wki]; kp = wf[8*8+wki];   // j=2 -> out W-1
            rA.x = km.x*vm.x + k0.x*v0.x + kp.x*vp.x;
            rA.y = km.y*vm.y + k0.y*v0.y + kp.y*vp.y;
            rA.z = km.z*vm.z + k0.z*v0.z + kp.z*vp.z;
            rA.w = km.w*vm.w + k0.w*v0.w + kp.w*vp.w;
            km = wf[1*8+wki]; k0 = wf[4*8+wki]; kp = wf[7*8+wki];   // j=1 -> out W
            rB.x = km.x*vm.x + k0.x*v0.x + kp.x*vp.x;
            rB.y = km.y*vm.y + k0.y*v0.y + kp.y*vp.y;
            rB.z = km.z*vm.z + k0.z*v0.z + kp.z*vp.z;
            rB.w = km.w*vm.w + k0.w*v0.w + kp.w*vp.w;
            km = wf[0*8+wki]; k0 = wf[3*8+wki]; kp = wf[6*8+wki];   // j=0 -> out W+1
            rC.x = km.x*vm.x + k0.x*v0.x + kp.x*vp.x;
            rC.y = km.y*vm.y + k0.y*v0.y + kp.y*vp.y;
            rC.z = km.z*vm.z + k0.z*v0.z + kp.z*vp.z;
            rC.w = km.w*vm.w + k0.w*v0.w + kp.w*vp.w;

            // rotate pipeline state
            pend.x = a0.x + rA.x; pend.y = a0.y + rA.y;
            pend.z = a0.z + rA.z; pend.w = a0.w + rA.w;
            a0.x = a1.x + rB.x; a0.y = a1.y + rB.y;
            a0.z = a1.z + rB.z; a0.w = a1.w + rB.w;
            a1 = rC;
            g2 = g1; g1 = v0;
            w2p = w2pf;
        }
    }
}

// ---------------------------------------------------------------------------
extern "C" void kernel_launch(void* const* d_in, const int* in_sizes, int n_in,
                              void* d_out, int out_size)
{
    const float* x   = (const float*)d_in[0];
    const float* w1  = (const float*)d_in[1];
    const float* b1  = (const float*)d_in[2];
    const float* w3  = (const float*)d_in[3];
    const float* b3  = (const float*)d_in[4];
    const float* gm  = (const float*)d_in[5];
    const float* bt  = (const float*)d_in[6];
    float* out = (float*)d_out;

    static int configured = 0;
    if (!configured) {
        cudaFuncSetAttribute(fused_all, cudaFuncAttributeMaxDynamicSharedMemorySize,
                             F_TOTAL * 4);
        configured = 1;
    }

    fused_all<<<BG, 512, F_TOTAL*4>>>(x, w1, b1, w3, b3, gm, bt, out);
}

// round 15
// speedup vs baseline: 1.1035x; 1.0515x over previous
#include <cuda_runtime.h>
#include <math.h>

// Problem shape (fixed by setup_inputs)
#define Bb   32
#define Hh   64
#define Ww   48
#define Cc   256
#define Dd   32
#define BG   256            // Bb * groups(8)
#define NPIX (Hh*Ww)        // 3072
#define LN_EPS 1e-3f

__device__ __forceinline__ float wsum(float v){
#pragma unroll
    for (int o = 16; o; o >>= 1) v += __shfl_xor_sync(0xffffffffu, v, o);
    return v;
}
__device__ __forceinline__ float wmax(float v){
#pragma unroll
    for (int o = 16; o; o >>= 1) v = fmaxf(v, __shfl_xor_sync(0xffffffffu, v, o));
    return v;
}

// Dynamic smem layout (floats):
#define F_ROW   0                  // s_row[64][32]
#define F_COLP  2048               // s_colp[4][48][32]; AFTER Phase C reused as s_w2[3072]
#define F_XH    8192               // s_xh[64][32]
#define F_XW    10240              // s_xw[48][32]
#define F_W1    11776              // smW[1024]; AFTER Phase B reused as s_weff[288]
#define F_S9    12800              // smS[288]
#define F_SA    13088              // sA[16][32]
#define F_SB    13600              // sB[16]
#define F_X11   13616              // x11[32]
#define F_C     13648              // s_c[32]  (x21*gamma)
#define F_SC    13680              // s_scal[4] (csum, cb, beff)
#define F_TOTAL 13684              // floats -> 54736 bytes

// ---------------------------------------------------------------------------
// GRAND FUSED kernel: pools, gates, x21/x11 softmaxes, LN stats, w2 field,
// projected conv + gate + output — one block (512 thr, 16 warps) per bg.
// launch_bounds(512,2): 2 blocks/SM -> all 256 blocks in ONE wave.
// ---------------------------------------------------------------------------
__global__ void __launch_bounds__(512, 2)
fused_all(const float* __restrict__ x,
          const float* __restrict__ w1x1,
          const float* __restrict__ b1,
          const float* __restrict__ w3,
          const float* __restrict__ b3,
          const float* __restrict__ gamma,
          const float* __restrict__ beta,
          float* __restrict__ out)
{
    extern __shared__ float sm[];
    float (*s_row)[Dd]       = (float(*)[Dd])(sm + F_ROW);
    float (*s_colp)[Ww][Dd]  = (float(*)[Ww][Dd])(sm + F_COLP);
    float (*s_xh)[Dd]        = (float(*)[Dd])(sm + F_XH);
    float (*s_xw)[Dd]        = (float(*)[Dd])(sm + F_XW);
    float *smW = sm + F_W1;
    float *smS = sm + F_S9;
    float (*sA)[Dd]          = (float(*)[Dd])(sm + F_SA);
    float *sB  = sm + F_SB;
    float *x11 = sm + F_X11;
    float *s_c = sm + F_C;
    float *s_scal = sm + F_SC;
    float *s_w2   = sm + F_COLP;   // overlay (valid after Phase C)
    float *s_weff = sm + F_W1;     // overlay (valid after Phase B)

    int bg = blockIdx.x;
    int b = bg >> 3, gi = bg & 7;
    int tid = threadIdx.x, lane = tid & 31, warp = tid >> 5;   // 16 warps
    int sg = lane >> 3, ch0 = (lane & 7) * 4;
    const float* xg = x + ((size_t)b*Hh)*Ww*Cc + gi*Dd + ch0;  // float4 base
    const float* xb = x + ((size_t)b*Hh)*Ww*Cc + gi*Dd + lane; // scalar base

    // stage conv1x1 weights (sync provided by the staged col-reduce below)
    for (int i = tid; i < Dd*Dd; i += 512) smW[i] = w1x1[i];

    // ---- Phase A: row means + col sums. Superslab structure (low regs). ----
    {
        float4 racc[4];
#pragma unroll
        for (int rr = 0; rr < 4; ++rr) racc[rr] = make_float4(0.f,0.f,0.f,0.f);
        int r0w = warp * 4;
        int slot = warp & 3, grp = warp >> 2;
#pragma unroll
        for (int ss = 0; ss < 3; ++ss) {
            float4 cacc[4];
#pragma unroll
            for (int s = 0; s < 4; ++s) cacc[s] = make_float4(0.f,0.f,0.f,0.f);
#pragma unroll
            for (int rr = 0; rr < 4; ++rr) {
                const float* rp = xg + (size_t)(r0w + rr)*Ww*Cc;
#pragma unroll
                for (int s = 0; s < 4; ++s) {
                    float4 v = *(const float4*)(rp + (size_t)(ss*16 + s*4 + sg)*Cc);
                    cacc[s].x += v.x; cacc[s].y += v.y; cacc[s].z += v.z; cacc[s].w += v.w;
                    racc[rr].x += v.x; racc[rr].y += v.y; racc[rr].z += v.z; racc[rr].w += v.w;
                }
            }
            // staged atomic-free cross-warp accumulation into s_colp[slot]
#pragma unroll
            for (int rd = 0; rd < 4; ++rd) {
                if (grp == rd) {
#pragma unroll
                    for (int s = 0; s < 4; ++s) {
                        float4* dst = (float4*)&s_colp[slot][ss*16 + s*4 + sg][ch0];
                        if (rd == 0) *dst = cacc[s];
                        else {
                            float4 t = *dst;
                            t.x += cacc[s].x; t.y += cacc[s].y;
                            t.z += cacc[s].z; t.w += cacc[s].w;
                            *dst = t;
                        }
                    }
                }
                __syncthreads();
            }
        }
        // row means
#pragma unroll
        for (int rr = 0; rr < 4; ++rr) {
            float4 rv = racc[rr];
#pragma unroll
            for (int o = 8; o <= 16; o <<= 1) {
                rv.x += __shfl_xor_sync(0xffffffffu, rv.x, o);
                rv.y += __shfl_xor_sync(0xffffffffu, rv.y, o);
                rv.z += __shfl_xor_sync(0xffffffffu, rv.z, o);
                rv.w += __shfl_xor_sync(0xffffffffu, rv.w, o);
            }
            if (sg == 0) {
                rv.x *= (1.f/Ww); rv.y *= (1.f/Ww); rv.z *= (1.f/Ww); rv.w *= (1.f/Ww);
                *(float4*)&s_row[r0w + rr][ch0] = rv;
            }
        }
    }
    __syncthreads();

    // ---- Phase B (warps 1..15) / Phase C (warp 0), concurrent ----
    if (warp > 0) {
        float bias = b1[lane];
        for (int p = warp - 1; p < Hh + Ww; p += 15) {
            float v;
            if (p < Hh) v = s_row[p][lane];
            else {
                int w = p - Hh;
                v = (s_colp[0][w][lane] + s_colp[1][w][lane]
                   + s_colp[2][w][lane] + s_colp[3][w][lane]) * (1.0f/Hh);
            }
            float acc = bias;
#pragma unroll
            for (int i = 0; i < Dd; ++i) {
                float vi = __shfl_sync(0xffffffffu, v, i);
                acc += vi * smW[i*Dd + lane];
            }
            float s = 1.f/(1.f + expf(-acc));
            if (p < Hh) s_xh[p][lane] = s;
            else        s_xw[p-Hh][lane] = s;
        }
    } else {
        int i = lane;
        float T = 0.f;
#pragma unroll 8
        for (int h = 0; h < Hh; ++h) T += s_row[h][i];
        T *= (float)Ww;
        float R0 = s_row[0     ][i] * (float)Ww;
        float RL = s_row[Hh - 1][i] * (float)Ww;
        float C0 = s_colp[0][0][i] + s_colp[1][0][i] + s_colp[2][0][i] + s_colp[3][0][i];
        float CL = s_colp[0][Ww-1][i] + s_colp[1][Ww-1][i] + s_colp[2][Ww-1][i] + s_colp[3][Ww-1][i];
        float ctl = xb[0];
        float ctr = xb[(size_t)(Ww-1)*Cc];
        float cbl = xb[((size_t)(Hh-1)*Ww)*Cc];
        float cbr = xb[((size_t)(Hh-1)*Ww + (Ww-1))*Cc];
#pragma unroll
        for (int dy = -1; dy <= 1; ++dy) {
#pragma unroll
            for (int dx = -1; dx <= 1; ++dx) {
                float eR = (dy == -1) ? RL : (dy == 1) ? R0 : 0.f;
                float eC = (dx == -1) ? CL : (dx == 1) ? C0 : 0.f;
                float corner = 0.f;
                if (dy == -1 && dx == -1) corner = cbr;
                if (dy == -1 && dx ==  1) corner = cbl;
                if (dy ==  1 && dx == -1) corner = ctr;
                if (dy ==  1 && dx ==  1) corner = ctl;
                smS[((dy+1)*3 + (dx+1))*Dd + i] = T - eR - eC + corner;
            }
        }
        __syncwarp();
        int e = lane;
        float acc = 0.f;
        for (int k = 0; k < 9; ++k) {
#pragma unroll
            for (int ii = 0; ii < Dd; ++ii)
                acc += w3[(k*Dd + ii)*Dd + e] * smS[k*Dd + ii];
        }
        float m2 = acc * (1.f/NPIX) + b3[e];
        float mx = wmax(m2);
        float pz = expf(m2 - mx);
        float ps = wsum(pz);
        float x21 = pz/ps;
        float cv = x21 * gamma[e];
        s_c[e] = cv;
        float cs  = wsum(cv);
        float cbv = wsum(x21 * beta[e]);
        if (e == 0) { s_scal[0] = cs; s_scal[1] = cbv; }
    }
    __syncthreads();
    // s_colp is dead from here on: its space becomes s_w2

    // ---- Phase D: LN-stat sweep + per-pixel w2 field (into smem) ----
    {
        float4 cvq = *(const float4*)&s_c[ch0];
        float csum = s_scal[0], cb = s_scal[1];
        float4 accA = make_float4(0.f,0.f,0.f,0.f);
        float accB = 0.f;
        int p0 = warp * 192;
#pragma unroll 2
        for (int j = 0; j < 192; j += 4) {
            int p = p0 + j + sg;
            int h = p / Ww, w = p - h*Ww;
            float4 gx = *(const float4*)(xg + (size_t)p*Cc);
            float4 xh = *(const float4*)&s_xh[h][ch0];
            float4 xw = *(const float4*)&s_xw[w][ch0];
            float4 y;
            y.x = gx.x*xh.x*xw.x; y.y = gx.y*xh.y*xw.y;
            y.z = gx.z*xh.z*xw.z; y.w = gx.w*xh.w*xw.w;
            float a  = (y.x + y.y) + (y.z + y.w);
            float bq = (y.x*y.x + y.y*y.y) + (y.z*y.z + y.w*y.w);
            float cy = (cvq.x*y.x + cvq.y*y.y) + (cvq.z*y.z + cvq.w*y.w);
#pragma unroll
            for (int o = 4; o; o >>= 1) {
                a  += __shfl_xor_sync(0xffffffffu, a,  o);
                bq += __shfl_xor_sync(0xffffffffu, bq, o);
                cy += __shfl_xor_sync(0xffffffffu, cy, o);
            }
            float mu = a * (1.f/Dd);
            float var = bq * (1.f/Dd) - mu*mu;
            float rs = rsqrtf(var + LN_EPS);
            accA.x += rs*y.x; accA.y += rs*y.y; accA.z += rs*y.z; accA.w += rs*y.w;
            accB += rs*mu;
            float w2v = rs * (cy - mu*csum) + cb;
            if ((lane & 7) == 0) s_w2[p] = w2v;
        }
#pragma unroll
        for (int o = 8; o <= 16; o <<= 1) {
            accA.x += __shfl_xor_sync(0xffffffffu, accA.x, o);
            accA.y += __shfl_xor_sync(0xffffffffu, accA.y, o);
            accA.z += __shfl_xor_sync(0xffffffffu, accA.z, o);
            accA.w += __shfl_xor_sync(0xffffffffu, accA.w, o);
        }
        if (sg == 0) *(float4*)&sA[warp][ch0] = accA;
        float bt = wsum(accB) * 0.125f;   // each pixel counted by 8 lanes
        if (lane == 0) sB[warp] = bt;
    }
    __syncthreads();

    // ---- Phase E: x11 softmax + beff (warp 0), then weff into smem ----
    if (warp == 0) {
        int e = lane;
        float A = 0.f, Bs = 0.f;
#pragma unroll
        for (int k = 0; k < 16; ++k) { A += sA[k][e]; Bs += sB[k]; }
        float v = gamma[e] * (A - Bs) * (1.f/NPIX) + beta[e];
        float mx = wmax(v);
        float p = expf(v - mx);
        float ps = wsum(p);
        float xv = p/ps;
        x11[e] = xv;
        float be = wsum(xv * b3[e]);
        if (e == 0) s_scal[2] = be;
    }
    __syncthreads();
    if (tid < 288) {
        const float4* wrow = (const float4*)(w3 + (size_t)tid*Dd);
        float acc = 0.f;
#pragma unroll
        for (int e4 = 0; e4 < 8; ++e4) {
            float4 wv = __ldg(&wrow[e4]);
            acc += wv.x*x11[e4*4+0] + wv.y*x11[e4*4+1]
                 + wv.z*x11[e4*4+2] + wv.w*x11[e4*4+3];
        }
        s_weff[tid] = acc;   // overlays smW (dead after Phase B)
    }
    __syncthreads();

    // ---- Phase F: conv march along w + gate + output.
    // 2 rows/warp x 16 lanes x float2 channels; taps in 18 REGISTERS.
    // 2 marches of 32 rows; one shfl ladder reduces both rows at once. ----
    {
        int cl = lane & 15, rr = lane >> 4;     // channel group / row-in-pair
        int ch = cl * 2;
        float2 wk2[9];
#pragma unroll
        for (int k = 0; k < 9; ++k)
            wk2[k] = *(const float2*)&s_weff[k*Dd + ch];
        float beff = s_scal[2];
        const int CS = Cc/2;                    // column stride (float2)
        const int RS = Ww*Cc/2;                 // row stride (float2)

#pragma unroll
        for (int m = 0; m < 2; ++m) {
            int r = m*32 + warp*2 + rr;         // 0..63
            const float2* rq = (const float2*)(x + ((size_t)b*Hh + r)*Ww*Cc + gi*Dd + ch);
            float2* oq = (float2*)(out + ((size_t)b*Hh + r)*Ww*Cc + gi*Dd + ch);
            const float* w2row = s_w2 + r*Ww;
            bool up = (r > 0), dn = (r < Hh-1);

            float2 a0 = make_float2(0.f,0.f), a1 = a0, pend = a0, g1 = a0, g2 = a0;
            float w2p = 0.f;

            for (int W = 0; W < 50; ++W) {
                // loads for source column W (rows r-1, r, r+1)
                float2 v0 = make_float2(0.f,0.f), vm = v0, vp = v0;
                if (W < Ww) {
                    v0 = rq[0];
                    if (up) vm = rq[-RS];
                    if (dn) vp = rq[ RS];
                }
                rq += CS;
                // prefetch w2 for output column W-1 (consumed next iteration)
                float w2pf = 0.f;
                if ((unsigned)(W-1) < (unsigned)Ww) w2pf = w2row[W-1];

                // emission for output column W-2 (both rows in one ladder)
                if (W >= 2) {
                    float conv = pend.x + pend.y;
                    conv += __shfl_xor_sync(0xffffffffu, conv, 8);
                    conv += __shfl_xor_sync(0xffffffffu, conv, 4);
                    conv += __shfl_xor_sync(0xffffffffu, conv, 2);
                    conv += __shfl_xor_sync(0xffffffffu, conv, 1);
                    float gate = __fdividef(1.f, 1.f + __expf(-(conv + beff + w2p)));
                    float2 o2;
                    o2.x = g2.x*gate; o2.y = g2.y*gate;
                    __stcs(oq, o2);
                    oq += CS;
                }

                // column-dots (taps in registers)
                float2 rA, rB, rC;
                rA.x = wk2[2].x*vm.x + wk2[5].x*v0.x + wk2[8].x*vp.x;
                rA.y = wk2[2].y*vm.y + wk2[5].y*v0.y + wk2[8].y*vp.y;
                rB.x = wk2[1].x*vm.x + wk2[4].x*v0.x + wk2[7].x*vp.x;
                rB.y = wk2[1].y*vm.y + wk2[4].y*v0.y + wk2[7].y*vp.y;
                rC.x = wk2[0].x*vm.x + wk2[3].x*v0.x + wk2[6].x*vp.x;
                rC.y = wk2[0].y*vm.y + wk2[3].y*v0.y + wk2[6].y*vp.y;

                // rotate pipeline state
                pend.x = a0.x + rA.x; pend.y = a0.y + rA.y;
                a0.x = a1.x + rB.x; a0.y = a1.y + rB.y;
                a1 = rC;
                g2 = g1; g1 = v0;
                w2p = w2pf;
            }
        }
    }
}

// ---------------------------------------------------------------------------
extern "C" void kernel_launch(void* const* d_in, const int* in_sizes, int n_in,
                              void* d_out, int out_size)
{
    const float* x   = (const float*)d_in[0];
    const float* w1  = (const float*)d_in[1];
    const float* b1  = (const float*)d_in[2];
    const float* w3  = (const float*)d_in[3];
    const float* b3  = (const float*)d_in[4];
    const float* gm  = (const float*)d_in[5];
    const float* bt  = (const float*)d_in[6];
    float* out = (float*)d_out;

    static int configured = 0;
    if (!configured) {
        cudaFuncSetAttribute(fused_all, cudaFuncAttributeMaxDynamicSharedMemorySize,
                             F_TOTAL * 4);
        configured = 1;
    }

    fused_all<<<BG, 512, F_TOTAL*4>>>(x, w1, b1, w3, b3, gm, bt, out);
}

// round 16
// speedup vs baseline: 1.2550x; 1.1373x over previous
#include <cuda_runtime.h>
#include <math.h>

// Problem shape (fixed by setup_inputs)
#define Bb   32
#define Hh   64
#define Ww   48
#define Cc   256
#define Dd   32
#define BG   256            // Bb * groups(8)
#define NPIX (Hh*Ww)        // 3072
#define LN_EPS 1e-3f

__device__ __forceinline__ float wsum(float v){
#pragma unroll
    for (int o = 16; o; o >>= 1) v += __shfl_xor_sync(0xffffffffu, v, o);
    return v;
}
__device__ __forceinline__ float wmax(float v){
#pragma unroll
    for (int o = 16; o; o >>= 1) v = fmaxf(v, __shfl_xor_sync(0xffffffffu, v, o));
    return v;
}

// Dynamic smem layout (floats):
#define F_ROW   0                  // s_row[64][32]
#define F_COLP  2048               // s_colp[4][48][32]; AFTER Phase C reused as s_w2[3072]
#define F_XH    8192               // s_xh[64][32]
#define F_XW    10240              // s_xw[48][32]
#define F_W1    11776              // smW[1024]; AFTER Phase B reused as s_weff[288]
#define F_S9    12800              // smS[288]
#define F_SA    13088              // sA[16][32]
#define F_SB    13600              // sB[16]
#define F_X11   13616              // x11[32]
#define F_C     13648              // s_c[32]  (x21*gamma)
#define F_SC    13680              // s_scal[4] (csum, cb, beff)
#define F_TOTAL 13684              // floats -> 54736 bytes

// ---------------------------------------------------------------------------
// GRAND FUSED kernel: pools, gates, x21/x11 softmaxes, LN stats, w2 field,
// projected conv + gate + output — one block (512 thr, 16 warps) per bg.
// launch_bounds(512,2): 2 blocks/SM -> all 256 blocks in ONE wave.
// ---------------------------------------------------------------------------
__global__ void __launch_bounds__(512, 2)
fused_all(const float* __restrict__ x,
          const float* __restrict__ w1x1,
          const float* __restrict__ b1,
          const float* __restrict__ w3,
          const float* __restrict__ b3,
          const float* __restrict__ gamma,
          const float* __restrict__ beta,
          float* __restrict__ out)
{
    extern __shared__ float sm[];
    float (*s_row)[Dd]       = (float(*)[Dd])(sm + F_ROW);
    float (*s_colp)[Ww][Dd]  = (float(*)[Ww][Dd])(sm + F_COLP);
    float (*s_xh)[Dd]        = (float(*)[Dd])(sm + F_XH);
    float (*s_xw)[Dd]        = (float(*)[Dd])(sm + F_XW);
    float *smW = sm + F_W1;
    float *smS = sm + F_S9;
    float (*sA)[Dd]          = (float(*)[Dd])(sm + F_SA);
    float *sB  = sm + F_SB;
    float *x11 = sm + F_X11;
    float *s_c = sm + F_C;
    float *s_scal = sm + F_SC;
    float *s_w2   = sm + F_COLP;   // overlay (valid after Phase C)
    float *s_weff = sm + F_W1;     // overlay (valid after Phase B)

    int bg = blockIdx.x;
    int b = bg >> 3, gi = bg & 7;
    int tid = threadIdx.x, lane = tid & 31, warp = tid >> 5;   // 16 warps
    int sg = lane >> 3, ch0 = (lane & 7) * 4;
    const float* xg = x + ((size_t)b*Hh)*Ww*Cc + gi*Dd + ch0;  // float4 base
    const float* xb = x + ((size_t)b*Hh)*Ww*Cc + gi*Dd + lane; // scalar base

    // stage conv1x1 weights (sync provided by the staged col-reduce below)
    for (int i = tid; i < Dd*Dd; i += 512) smW[i] = w1x1[i];

    // ---- Phase A: row means + col sums. Superslab structure (low regs). ----
    {
        float4 racc[4];
#pragma unroll
        for (int rr = 0; rr < 4; ++rr) racc[rr] = make_float4(0.f,0.f,0.f,0.f);
        int r0w = warp * 4;
        int slot = warp & 3, grp = warp >> 2;
#pragma unroll
        for (int ss = 0; ss < 3; ++ss) {
            float4 cacc[4];
#pragma unroll
            for (int s = 0; s < 4; ++s) cacc[s] = make_float4(0.f,0.f,0.f,0.f);
#pragma unroll
            for (int rr = 0; rr < 4; ++rr) {
                const float* rp = xg + (size_t)(r0w + rr)*Ww*Cc;
#pragma unroll
                for (int s = 0; s < 4; ++s) {
                    float4 v = *(const float4*)(rp + (size_t)(ss*16 + s*4 + sg)*Cc);
                    cacc[s].x += v.x; cacc[s].y += v.y; cacc[s].z += v.z; cacc[s].w += v.w;
                    racc[rr].x += v.x; racc[rr].y += v.y; racc[rr].z += v.z; racc[rr].w += v.w;
                }
            }
            // staged atomic-free cross-warp accumulation into s_colp[slot]
#pragma unroll
            for (int rd = 0; rd < 4; ++rd) {
                if (grp == rd) {
#pragma unroll
                    for (int s = 0; s < 4; ++s) {
                        float4* dst = (float4*)&s_colp[slot][ss*16 + s*4 + sg][ch0];
                        if (rd == 0) *dst = cacc[s];
                        else {
                            float4 t = *dst;
                            t.x += cacc[s].x; t.y += cacc[s].y;
                            t.z += cacc[s].z; t.w += cacc[s].w;
                            *dst = t;
                        }
                    }
                }
                __syncthreads();
            }
        }
        // row means
#pragma unroll
        for (int rr = 0; rr < 4; ++rr) {
            float4 rv = racc[rr];
#pragma unroll
            for (int o = 8; o <= 16; o <<= 1) {
                rv.x += __shfl_xor_sync(0xffffffffu, rv.x, o);
                rv.y += __shfl_xor_sync(0xffffffffu, rv.y, o);
                rv.z += __shfl_xor_sync(0xffffffffu, rv.z, o);
                rv.w += __shfl_xor_sync(0xffffffffu, rv.w, o);
            }
            if (sg == 0) {
                rv.x *= (1.f/Ww); rv.y *= (1.f/Ww); rv.z *= (1.f/Ww); rv.w *= (1.f/Ww);
                *(float4*)&s_row[r0w + rr][ch0] = rv;
            }
        }
    }
    __syncthreads();

    // ---- Phase B (warps 1..15) / Phase C (warp 0), concurrent ----
    if (warp > 0) {
        float bias = b1[lane];
        for (int p = warp - 1; p < Hh + Ww; p += 15) {
            float v;
            if (p < Hh) v = s_row[p][lane];
            else {
                int w = p - Hh;
                v = (s_colp[0][w][lane] + s_colp[1][w][lane]
                   + s_colp[2][w][lane] + s_colp[3][w][lane]) * (1.0f/Hh);
            }
            float acc = bias;
#pragma unroll
            for (int i = 0; i < Dd; ++i) {
                float vi = __shfl_sync(0xffffffffu, v, i);
                acc += vi * smW[i*Dd + lane];
            }
            float s = 1.f/(1.f + expf(-acc));
            if (p < Hh) s_xh[p][lane] = s;
            else        s_xw[p-Hh][lane] = s;
        }
    } else {
        int i = lane;
        float T = 0.f;
#pragma unroll 8
        for (int h = 0; h < Hh; ++h) T += s_row[h][i];
        T *= (float)Ww;
        float R0 = s_row[0     ][i] * (float)Ww;
        float RL = s_row[Hh - 1][i] * (float)Ww;
        float C0 = s_colp[0][0][i] + s_colp[1][0][i] + s_colp[2][0][i] + s_colp[3][0][i];
        float CL = s_colp[0][Ww-1][i] + s_colp[1][Ww-1][i] + s_colp[2][Ww-1][i] + s_colp[3][Ww-1][i];
        float ctl = xb[0];
        float ctr = xb[(size_t)(Ww-1)*Cc];
        float cbl = xb[((size_t)(Hh-1)*Ww)*Cc];
        float cbr = xb[((size_t)(Hh-1)*Ww + (Ww-1))*Cc];
#pragma unroll
        for (int dy = -1; dy <= 1; ++dy) {
#pragma unroll
            for (int dx = -1; dx <= 1; ++dx) {
                float eR = (dy == -1) ? RL : (dy == 1) ? R0 : 0.f;
                float eC = (dx == -1) ? CL : (dx == 1) ? C0 : 0.f;
                float corner = 0.f;
                if (dy == -1 && dx == -1) corner = cbr;
                if (dy == -1 && dx ==  1) corner = cbl;
                if (dy ==  1 && dx == -1) corner = ctr;
                if (dy ==  1 && dx ==  1) corner = ctl;
                smS[((dy+1)*3 + (dx+1))*Dd + i] = T - eR - eC + corner;
            }
        }
        __syncwarp();
        int e = lane;
        float acc = 0.f;
        for (int k = 0; k < 9; ++k) {
#pragma unroll
            for (int ii = 0; ii < Dd; ++ii)
                acc += w3[(k*Dd + ii)*Dd + e] * smS[k*Dd + ii];
        }
        float m2 = acc * (1.f/NPIX) + b3[e];
        float mx = wmax(m2);
        float pz = expf(m2 - mx);
        float ps = wsum(pz);
        float x21 = pz/ps;
        float cv = x21 * gamma[e];
        s_c[e] = cv;
        float cs  = wsum(cv);
        float cbv = wsum(x21 * beta[e]);
        if (e == 0) { s_scal[0] = cs; s_scal[1] = cbv; }
    }
    __syncthreads();
    // s_colp is dead from here on: its space becomes s_w2

    // ---- Phase D: LN-stat sweep + per-pixel w2 field (into smem) ----
    {
        float4 cvq = *(const float4*)&s_c[ch0];
        float csum = s_scal[0], cb = s_scal[1];
        float4 accA = make_float4(0.f,0.f,0.f,0.f);
        float accB = 0.f;
        int p0 = warp * 192;
#pragma unroll 2
        for (int j = 0; j < 192; j += 4) {
            int p = p0 + j + sg;
            int h = p / Ww, w = p - h*Ww;
            float4 gx = *(const float4*)(xg + (size_t)p*Cc);
            float4 xh = *(const float4*)&s_xh[h][ch0];
            float4 xw = *(const float4*)&s_xw[w][ch0];
            float4 y;
            y.x = gx.x*xh.x*xw.x; y.y = gx.y*xh.y*xw.y;
            y.z = gx.z*xh.z*xw.z; y.w = gx.w*xh.w*xw.w;
            float a  = (y.x + y.y) + (y.z + y.w);
            float bq = (y.x*y.x + y.y*y.y) + (y.z*y.z + y.w*y.w);
            float cy = (cvq.x*y.x + cvq.y*y.y) + (cvq.z*y.z + cvq.w*y.w);
#pragma unroll
            for (int o = 4; o; o >>= 1) {
                a  += __shfl_xor_sync(0xffffffffu, a,  o);
                bq += __shfl_xor_sync(0xffffffffu, bq, o);
                cy += __shfl_xor_sync(0xffffffffu, cy, o);
            }
            float mu = a * (1.f/Dd);
            float var = bq * (1.f/Dd) - mu*mu;
            float rs = rsqrtf(var + LN_EPS);
            accA.x += rs*y.x; accA.y += rs*y.y; accA.z += rs*y.z; accA.w += rs*y.w;
            accB += rs*mu;
            float w2v = rs * (cy - mu*csum) + cb;
            if ((lane & 7) == 0) s_w2[p] = w2v;
        }
#pragma unroll
        for (int o = 8; o <= 16; o <<= 1) {
            accA.x += __shfl_xor_sync(0xffffffffu, accA.x, o);
            accA.y += __shfl_xor_sync(0xffffffffu, accA.y, o);
            accA.z += __shfl_xor_sync(0xffffffffu, accA.z, o);
            accA.w += __shfl_xor_sync(0xffffffffu, accA.w, o);
        }
        if (sg == 0) *(float4*)&sA[warp][ch0] = accA;
        float bt = wsum(accB) * 0.125f;   // each pixel counted by 8 lanes
        if (lane == 0) sB[warp] = bt;
    }
    __syncthreads();

    // ---- Phase E: x11 softmax + beff (warp 0), then weff into smem ----
    if (warp == 0) {
        int e = lane;
        float A = 0.f, Bs = 0.f;
#pragma unroll
        for (int k = 0; k < 16; ++k) { A += sA[k][e]; Bs += sB[k]; }
        float v = gamma[e] * (A - Bs) * (1.f/NPIX) + beta[e];
        float mx = wmax(v);
        float p = expf(v - mx);
        float ps = wsum(p);
        float xv = p/ps;
        x11[e] = xv;
        float be = wsum(xv * b3[e]);
        if (e == 0) s_scal[2] = be;
    }
    __syncthreads();
    if (tid < 288) {
        const float4* wrow = (const float4*)(w3 + (size_t)tid*Dd);
        float acc = 0.f;
#pragma unroll
        for (int e4 = 0; e4 < 8; ++e4) {
            float4 wv = __ldg(&wrow[e4]);
            acc += wv.x*x11[e4*4+0] + wv.y*x11[e4*4+1]
                 + wv.z*x11[e4*4+2] + wv.w*x11[e4*4+3];
        }
        s_weff[tid] = acc;   // overlays smW (dead after Phase B)
    }
    __syncthreads();

    // ---- Phase F: DOUBLE-BUFFERED conv march along w + gate + output.
    // 2 rows/warp x 16 lanes x float2 channels; taps in 18 registers.
    // Loads for column W+1 issue before row-dots consume column W. ----
    {
        int cl = lane & 15, rr = lane >> 4;     // channel group / row-in-pair
        int ch = cl * 2;
        float2 wk2[9];
#pragma unroll
        for (int k = 0; k < 9; ++k)
            wk2[k] = *(const float2*)&s_weff[k*Dd + ch];
        float beff = s_scal[2];
        const int CS = Cc/2;                    // column stride (float2)
        const int RS = Ww*Cc/2;                 // row stride (float2)

#pragma unroll
        for (int m = 0; m < 2; ++m) {
            int r = m*32 + warp*2 + rr;         // 0..63
            const float2* rq = (const float2*)(x + ((size_t)b*Hh + r)*Ww*Cc + gi*Dd + ch);
            float2* oq = (float2*)(out + ((size_t)b*Hh + r)*Ww*Cc + gi*Dd + ch);
            const float* w2row = s_w2 + r*Ww;
            bool up = (r > 0), dn = (r < Hh-1);

            const float2 z2 = make_float2(0.f,0.f);
            float2 a0 = z2, a1 = z2, pend = z2, g1 = z2, g2 = z2;
            // preload column 0
            float2 c0 = rq[0];
            float2 cm = up ? rq[-RS] : z2;
            float2 cp = dn ? rq[ RS] : z2;
            rq += CS;

            for (int W = 0; W < 50; ++W) {
                // 1) prefetch taps for column W+1 (consumed next iteration)
                float2 n0 = z2, nm = z2, np = z2;
                if (W + 1 < Ww) {
                    n0 = rq[0];
                    if (up) nm = rq[-RS];
                    if (dn) np = rq[ RS];
                }
                rq += CS;

                // 2) emission for output column W-2 (uses only prior-step state;
                //    w2 read directly from smem, hidden under the shfl ladder)
                if (W >= 2) {
                    float w2v = w2row[W-2];
                    float conv = pend.x + pend.y;
                    conv += __shfl_xor_sync(0xffffffffu, conv, 8);
                    conv += __shfl_xor_sync(0xffffffffu, conv, 4);
                    conv += __shfl_xor_sync(0xffffffffu, conv, 2);
                    conv += __shfl_xor_sync(0xffffffffu, conv, 1);
                    float gate = __fdividef(1.f, 1.f + __expf(-(conv + beff + w2v)));
                    float2 o2;
                    o2.x = g2.x*gate; o2.y = g2.y*gate;
                    __stcs(oq, o2);
                    oq += CS;
                }

                // 3) column-dots for column W (loaded LAST iteration)
                float2 rA, rB, rC;
                rA.x = wk2[2].x*cm.x + wk2[5].x*c0.x + wk2[8].x*cp.x;
                rA.y = wk2[2].y*cm.y + wk2[5].y*c0.y + wk2[8].y*cp.y;
                rB.x = wk2[1].x*cm.x + wk2[4].x*c0.x + wk2[7].x*cp.x;
                rB.y = wk2[1].y*cm.y + wk2[4].y*c0.y + wk2[7].y*cp.y;
                rC.x = wk2[0].x*cm.x + wk2[3].x*c0.x + wk2[6].x*cp.x;
                rC.y = wk2[0].y*cm.y + wk2[3].y*c0.y + wk2[6].y*cp.y;

                // 4) rotate pipeline state
                pend.x = a0.x + rA.x; pend.y = a0.y + rA.y;
                a0.x = a1.x + rB.x; a0.y = a1.y + rB.y;
                a1 = rC;
                g2 = g1; g1 = c0;
                cm = nm; c0 = n0; cp = np;
            }
        }
    }
}

// ---------------------------------------------------------------------------
extern "C" void kernel_launch(void* const* d_in, const int* in_sizes, int n_in,
                              void* d_out, int out_size)
{
    const float* x   = (const float*)d_in[0];
    const float* w1  = (const float*)d_in[1];
    const float* b1  = (const float*)d_in[2];
    const float* w3  = (const float*)d_in[3];
    const float* b3  = (const float*)d_in[4];
    const float* gm  = (const float*)d_in[5];
    const float* bt  = (const float*)d_in[6];
    float* out = (float*)d_out;

    static int configured = 0;
    if (!configured) {
        cudaFuncSetAttribute(fused_all, cudaFuncAttributeMaxDynamicSharedMemorySize,
                             F_TOTAL * 4);
        configured = 1;
    }

    fused_all<<<BG, 512, F_TOTAL*4>>>(x, w1, b1, w3, b3, gm, bt, out);
}